// round 3
// baseline (speedup 1.0000x reference)
#include <cuda_runtime.h>
#include <cuda_bf16.h>
#include <cstdint>
#include <cstddef>

// Problem dims
#define TT 512
#define BB 64
#define DD 1024
#define HH 1024
#define FOURH 4096
#define TBH (TT * BB * HH)   // 33554432
#define BH  (BB * HH)        // 65536

// Persistent-kernel config
#define NCTA 128          // <= 148 SMs, 1 CTA/SM -> co-resident
#define NTHR 256
#define NJ 8              // hidden columns per CTA (8 * 128 = 1024)

// ---------------- scratch (static device allocations are the allowed path) ----
__device__ float g_gx[(size_t)TT * FOURH * BB];   // 512 MB: Gx[t][j][b]
__device__ float g_h[2][BH];                      // h double buffer
__device__ unsigned int g_bar[TT];                // per-step grid barrier counters

// ---------------- init: zero barrier counters (runs every launch/replay) ------
__global__ void init_bar_kernel() {
    int i = threadIdx.x;
    if (i < TT) g_bar[i] = 0u;
}

// ---------------- Phase 1: Gx[t][j][b] = bias[j] + sum_d X[t,b,d]*W_ih[j,d] ---
// SGEMM: M = T*B (rows m -> (t = m>>6, b = m&63)), N = 4096, K = 1024. fp32.
#define BM 128
#define BN 128
#define BKK 16
__global__ __launch_bounds__(256, 1)
void gemm_xwih_kernel(const float* __restrict__ X,
                      const float* __restrict__ W,     // W_ih [4096][1024]
                      const float* __restrict__ b_ih,
                      const float* __restrict__ b_hh) {
    __shared__ float As[BKK][BM];
    __shared__ float Bs[BKK][BN];

    const int tid = threadIdx.x;
    const int m0 = blockIdx.y * BM;
    const int n0 = blockIdx.x * BN;
    const int tm = (tid >> 4) * 8;   // m micro-offset (8 consecutive rows)
    const int tn = (tid & 15) * 8;   // n micro-offset

    float acc[8][8];
#pragma unroll
    for (int i = 0; i < 8; i++)
#pragma unroll
        for (int j = 0; j < 8; j++) acc[i][j] = 0.f;

    for (int k0 = 0; k0 < DD; k0 += BKK) {
#pragma unroll
        for (int r = 0; r < 2; r++) {
            int idx = tid + r * 256;       // 0..511
            int m   = idx >> 2;            // 0..127
            int kq  = (idx & 3) * 4;       // 0,4,8,12
            float4 va = *(const float4*)(X + (size_t)(m0 + m) * DD + k0 + kq);
            As[kq + 0][m] = va.x; As[kq + 1][m] = va.y;
            As[kq + 2][m] = va.z; As[kq + 3][m] = va.w;
            float4 vb = *(const float4*)(W + (size_t)(n0 + m) * DD + k0 + kq);
            Bs[kq + 0][m] = vb.x; Bs[kq + 1][m] = vb.y;
            Bs[kq + 2][m] = vb.z; Bs[kq + 3][m] = vb.w;
        }
        __syncthreads();

#pragma unroll
        for (int k = 0; k < BKK; k++) {
            float4 a0 = *(const float4*)&As[k][tm];
            float4 a1 = *(const float4*)&As[k][tm + 4];
            float4 c0 = *(const float4*)&Bs[k][tn];
            float4 c1 = *(const float4*)&Bs[k][tn + 4];
            float av[8] = {a0.x, a0.y, a0.z, a0.w, a1.x, a1.y, a1.z, a1.w};
            float bv[8] = {c0.x, c0.y, c0.z, c0.w, c1.x, c1.y, c1.z, c1.w};
#pragma unroll
            for (int i = 0; i < 8; i++)
#pragma unroll
                for (int j = 0; j < 8; j++)
                    acc[i][j] += av[i] * bv[j];
        }
        __syncthreads();
    }

    // Epilogue: Gx[t][j][b], b-contiguous stores (2x float4 per j)
    const int m = m0 + tm;            // 8 consecutive rows, same t (tm % 64 <= 56)
    const int t = m >> 6;
    const int b = m & 63;
#pragma unroll
    for (int j = 0; j < 8; j++) {
        int jg = n0 + tn + j;
        float bias = b_ih[jg] + b_hh[jg];
        float* dst = g_gx + ((size_t)t * FOURH + jg) * BB + b;
        float4 v0 = make_float4(acc[0][j] + bias, acc[1][j] + bias,
                                acc[2][j] + bias, acc[3][j] + bias);
        float4 v1 = make_float4(acc[4][j] + bias, acc[5][j] + bias,
                                acc[6][j] + bias, acc[7][j] + bias);
        *(float4*)dst       = v0;
        *(float4*)(dst + 4) = v1;
    }
}

// ---------------- Phase 2: persistent sequential LSTM --------------------------
// CTA ct owns hidden columns n = ct*8 .. ct*8+7 and all 4 gates of them:
// 32 W_hh rows (128 KB) cached in shared for all 512 steps; c in registers.
#define HS_STRIDE 129
#define SMEM_P2 ((32 * HH + BB * HS_STRIDE) * 4)   // 164096 bytes

__device__ __forceinline__ float sigmoidf_(float x) {
    return 1.0f / (1.0f + __expf(-x));
}

__global__ __launch_bounds__(NTHR, 1)
void lstm_seq_kernel(const float* __restrict__ h0,
                     const float* __restrict__ c0,
                     const float* __restrict__ Whh,   // [4096][1024]
                     float* __restrict__ out) {
    extern __shared__ float sm[];
    float* Wsh = sm;                  // [32][1024]
    float* hs  = sm + 32 * HH;        // [64][129]
    float* gsh = hs;                  // reused as gates [32][64] after compute

    const int tid = threadIdx.x;
    const int ct  = blockIdx.x;       // 0..127
    const int b0  = tid & 31;
    const int jq  = tid >> 5;         // 0..7 -> handles local j = jq*4 .. jq*4+3

    // ---- load W_hh slice into shared (once) ----
    {
        const float4* Wv = (const float4*)Whh;
        float4* Ws4 = (float4*)Wsh;
        for (int idx = tid; idx < 32 * 256; idx += NTHR) {
            int row  = idx >> 8;                 // local j 0..31
            int col  = idx & 255;                // float4 within row
            int gate = row >> 3, nl = row & 7;
            size_t jg = (size_t)gate * 1024 + ct * NJ + nl;
            Ws4[row * 256 + col] = Wv[jg * 256 + col];
        }
    }

    // ---- cell state in registers: items (b, nl) ----
    float c_reg[2];
#pragma unroll
    for (int r = 0; r < 2; r++) {
        int item = tid + NTHR * r;       // 0..511
        int b  = item & 63;
        int nl = item >> 6;              // 0..7
        c_reg[r] = c0[b * HH + ct * NJ + nl];
    }
    __syncthreads();

    // thread's 4 local gate-columns -> global j and Gx row base (constant over t)
    int jglob[4];
#pragma unroll
    for (int jj = 0; jj < 4; jj++) {
        int jl = jq * 4 + jj;
        jglob[jj] = (jl >> 3) * 1024 + ct * NJ + (jl & 7);
    }

    for (int t = 0; t < TT; t++) {
        const float* hsrc = (t == 0) ? h0 : g_h[t & 1];
        float acc[4][2];
#pragma unroll
        for (int jj = 0; jj < 4; jj++) { acc[jj][0] = 0.f; acc[jj][1] = 0.f; }

        for (int kc = 0; kc < HH; kc += 128) {
            __syncthreads();   // hs free for rewrite
            {
                int kq = tid & 31;          // float4 index within 128-chunk
                int bg = tid >> 5;          // 0..7
#pragma unroll
                for (int i = 0; i < 8; i++) {
                    int b = bg + 8 * i;
                    float4 v = __ldcg((const float4*)(hsrc + (size_t)b * HH + kc) + kq);
                    float* dst = hs + b * HS_STRIDE + 4 * kq;
                    dst[0] = v.x; dst[1] = v.y; dst[2] = v.z; dst[3] = v.w;
                }
            }
            __syncthreads();

            const float4* Wp0 = (const float4*)(Wsh + (jq * 4 + 0) * HH + kc);
            const float4* Wp1 = (const float4*)(Wsh + (jq * 4 + 1) * HH + kc);
            const float4* Wp2 = (const float4*)(Wsh + (jq * 4 + 2) * HH + kc);
            const float4* Wp3 = (const float4*)(Wsh + (jq * 4 + 3) * HH + kc);
            const float* hpa = hs + b0 * HS_STRIDE;
            const float* hpb = hs + (b0 + 32) * HS_STRIDE;

#pragma unroll 8
            for (int k4 = 0; k4 < 32; k4++) {
                float4 w4[4] = {Wp0[k4], Wp1[k4], Wp2[k4], Wp3[k4]};
                const float* wf = (const float*)&w4[0];
                float hva[4], hvb[4];
#pragma unroll
                for (int c = 0; c < 4; c++) {
                    hva[c] = hpa[k4 * 4 + c];
                    hvb[c] = hpb[k4 * 4 + c];
                }
#pragma unroll
                for (int jj = 0; jj < 4; jj++)
#pragma unroll
                    for (int c = 0; c < 4; c++) {
                        float w = wf[jj * 4 + c];
                        acc[jj][0] += w * hva[c];
                        acc[jj][1] += w * hvb[c];
                    }
            }
        }

        // add precomputed input projection (coalesced: b-contiguous)
#pragma unroll
        for (int jj = 0; jj < 4; jj++) {
            const float* gp = g_gx + ((size_t)t * FOURH + jglob[jj]) * BB;
            acc[jj][0] += __ldcs(gp + b0);
            acc[jj][1] += __ldcs(gp + b0 + 32);
        }

        __syncthreads();   // everyone done reading hs -> safe to write gsh (alias)
#pragma unroll
        for (int jj = 0; jj < 4; jj++) {
            int jl = jq * 4 + jj;
            gsh[jl * 64 + b0]      = acc[jj][0];
            gsh[jl * 64 + b0 + 32] = acc[jj][1];
        }
        __syncthreads();

        // elementwise cell update
        float* hdst = g_h[(t + 1) & 1];
#pragma unroll
        for (int r = 0; r < 2; r++) {
            int item = tid + NTHR * r;
            int b  = item & 63;
            int nl = item >> 6;
            float ig = gsh[(0  + nl) * 64 + b];
            float fg = gsh[(8  + nl) * 64 + b];
            float gg = gsh[(16 + nl) * 64 + b];
            float og = gsh[(24 + nl) * 64 + b];
            float iv = sigmoidf_(ig);
            float fv = sigmoidf_(fg);
            float gv = tanhf(gg);
            float ov = sigmoidf_(og);
            float cv = fv * c_reg[r] + iv * gv;
            float hv = ov * tanhf(cv);
            c_reg[r] = cv;
            int col = ct * NJ + nl;
            out[(size_t)t * BH + b * HH + col] = hv;
            __stcg(hdst + b * HH + col, hv);
            if (t == TT - 1) {
                out[(size_t)TBH + b * HH + col]      = hv;   // h_T
                out[(size_t)TBH + BH + b * HH + col] = cv;   // c_T
            }
        }

        // ---- grid barrier (release h writes, then arrive/spin) ----
        __threadfence();
        __syncthreads();
        if (tid == 0) {
            atomicAdd(&g_bar[t], 1u);
            while (*((volatile unsigned int*)&g_bar[t]) < (unsigned)NCTA) { }
            __threadfence();
        }
        __syncthreads();
    }
}

// ---------------- launch --------------------------------------------------------
extern "C" void kernel_launch(void* const* d_in, const int* in_sizes, int n_in,
                              void* d_out, int out_size) {
    const float* X    = (const float*)d_in[0];   // [T,B,D]
    const float* h0   = (const float*)d_in[1];   // [B,H]
    const float* c0   = (const float*)d_in[2];   // [B,H]
    const float* Wih  = (const float*)d_in[3];   // [4H,D]
    const float* Whh  = (const float*)d_in[4];   // [4H,H]
    const float* b_ih = (const float*)d_in[5];   // [4H]
    const float* b_hh = (const float*)d_in[6];   // [4H]
    float* out = (float*)d_out;

    cudaFuncSetAttribute(lstm_seq_kernel,
                         cudaFuncAttributeMaxDynamicSharedMemorySize, SMEM_P2);

    init_bar_kernel<<<1, TT>>>();

    dim3 g1(FOURH / BN, (TT * BB) / BM);   // (32, 256)
    gemm_xwih_kernel<<<g1, 256>>>(X, Wih, b_ih, b_hh);

    lstm_seq_kernel<<<NCTA, NTHR, SMEM_P2>>>(h0, c0, Whh, out);
}

// round 6
// speedup vs baseline: 1.0011x; 1.0011x over previous
#include <cuda_runtime.h>
#include <cuda_bf16.h>
#include <cstdint>
#include <cstddef>

// Problem dims
#define TT 512
#define BB 64
#define DD 1024
#define HH 1024
#define FOURH 4096
#define TBH (TT * BB * HH)   // 33554432
#define BH  (BB * HH)        // 65536

// Persistent-kernel config
#define NCTA 128          // <= 148 SMs, 1 CTA/SM -> co-resident
#define NTHR 256
#define NJ 8              // hidden columns per CTA (8 * 128 = 1024)

// ---------------- scratch (static device allocations are the allowed path) ----
__device__ float g_gx[(size_t)TT * FOURH * BB];   // 512 MB: Gx[t][j][b]
__device__ float g_h[2][BH];                      // h double buffer
__device__ unsigned int g_bar[TT];                // per-step grid barrier counters

// ---------------- init: zero barrier counters (runs every launch/replay) ------
__global__ void init_bar_kernel() {
    int i = threadIdx.x;
    if (i < TT) g_bar[i] = 0u;
}

// ---------------- Phase 1: Gx[t][j][b] = bias[j] + sum_d X[t,b,d]*W_ih[j,d] ---
// SGEMM: M = T*B (rows m -> (t = m>>6, b = m&63)), N = 4096, K = 1024. fp32.
#define BM 128
#define BN 128
#define BKK 16
__global__ __launch_bounds__(256, 1)
void gemm_xwih_kernel(const float* __restrict__ X,
                      const float* __restrict__ W,     // W_ih [4096][1024]
                      const float* __restrict__ b_ih,
                      const float* __restrict__ b_hh) {
    __shared__ float As[BKK][BM];
    __shared__ float Bs[BKK][BN];

    const int tid = threadIdx.x;
    const int m0 = blockIdx.y * BM;
    const int n0 = blockIdx.x * BN;
    const int tm = (tid >> 4) * 8;   // m micro-offset (8 consecutive rows)
    const int tn = (tid & 15) * 8;   // n micro-offset

    float acc[8][8];
#pragma unroll
    for (int i = 0; i < 8; i++)
#pragma unroll
        for (int j = 0; j < 8; j++) acc[i][j] = 0.f;

    for (int k0 = 0; k0 < DD; k0 += BKK) {
#pragma unroll
        for (int r = 0; r < 2; r++) {
            int idx = tid + r * 256;       // 0..511
            int m   = idx >> 2;            // 0..127
            int kq  = (idx & 3) * 4;       // 0,4,8,12
            float4 va = *(const float4*)(X + (size_t)(m0 + m) * DD + k0 + kq);
            As[kq + 0][m] = va.x; As[kq + 1][m] = va.y;
            As[kq + 2][m] = va.z; As[kq + 3][m] = va.w;
            float4 vb = *(const float4*)(W + (size_t)(n0 + m) * DD + k0 + kq);
            Bs[kq + 0][m] = vb.x; Bs[kq + 1][m] = vb.y;
            Bs[kq + 2][m] = vb.z; Bs[kq + 3][m] = vb.w;
        }
        __syncthreads();

#pragma unroll
        for (int k = 0; k < BKK; k++) {
            float4 a0 = *(const float4*)&As[k][tm];
            float4 a1 = *(const float4*)&As[k][tm + 4];
            float4 c0 = *(const float4*)&Bs[k][tn];
            float4 c1 = *(const float4*)&Bs[k][tn + 4];
            float av[8] = {a0.x, a0.y, a0.z, a0.w, a1.x, a1.y, a1.z, a1.w};
            float bv[8] = {c0.x, c0.y, c0.z, c0.w, c1.x, c1.y, c1.z, c1.w};
#pragma unroll
            for (int i = 0; i < 8; i++)
#pragma unroll
                for (int j = 0; j < 8; j++)
                    acc[i][j] += av[i] * bv[j];
        }
        __syncthreads();
    }

    // Epilogue: Gx[t][j][b], b-contiguous stores (2x float4 per j)
    const int m = m0 + tm;            // 8 consecutive rows, same t (tm % 64 <= 56)
    const int t = m >> 6;
    const int b = m & 63;
#pragma unroll
    for (int j = 0; j < 8; j++) {
        int jg = n0 + tn + j;
        float bias = b_ih[jg] + b_hh[jg];
        float* dst = g_gx + ((size_t)t * FOURH + jg) * BB + b;
        float4 v0 = make_float4(acc[0][j] + bias, acc[1][j] + bias,
                                acc[2][j] + bias, acc[3][j] + bias);
        float4 v1 = make_float4(acc[4][j] + bias, acc[5][j] + bias,
                                acc[6][j] + bias, acc[7][j] + bias);
        *(float4*)dst       = v0;
        *(float4*)(dst + 4) = v1;
    }
}

// ---------------- Phase 2: persistent sequential LSTM --------------------------
// CTA ct owns hidden columns n = ct*8 .. ct*8+7 and all 4 gates of them:
// 32 W_hh rows (128 KB) cached in shared for all 512 steps; c in registers.
#define HS_STRIDE 129
#define SMEM_P2 ((32 * HH + BB * HS_STRIDE) * 4)   // 164096 bytes

__device__ __forceinline__ float sigmoidf_(float x) {
    return 1.0f / (1.0f + __expf(-x));
}

__global__ __launch_bounds__(NTHR, 1)
void lstm_seq_kernel(const float* __restrict__ h0,
                     const float* __restrict__ c0,
                     const float* __restrict__ Whh,   // [4096][1024]
                     float* __restrict__ out) {
    extern __shared__ float sm[];
    float* Wsh = sm;                  // [32][1024]
    float* hs  = sm + 32 * HH;        // [64][129]
    float* gsh = hs;                  // reused as gates [32][64] after compute

    const int tid = threadIdx.x;
    const int ct  = blockIdx.x;       // 0..127
    const int b0  = tid & 31;
    const int jq  = tid >> 5;         // 0..7 -> handles local j = jq*4 .. jq*4+3

    // ---- load W_hh slice into shared (once) ----
    {
        const float4* Wv = (const float4*)Whh;
        float4* Ws4 = (float4*)Wsh;
        for (int idx = tid; idx < 32 * 256; idx += NTHR) {
            int row  = idx >> 8;                 // local j 0..31
            int col  = idx & 255;                // float4 within row
            int gate = row >> 3, nl = row & 7;
            size_t jg = (size_t)gate * 1024 + ct * NJ + nl;
            Ws4[row * 256 + col] = Wv[jg * 256 + col];
        }
    }

    // ---- cell state in registers: items (b, nl) ----
    float c_reg[2];
#pragma unroll
    for (int r = 0; r < 2; r++) {
        int item = tid + NTHR * r;       // 0..511
        int b  = item & 63;
        int nl = item >> 6;              // 0..7
        c_reg[r] = c0[b * HH + ct * NJ + nl];
    }
    __syncthreads();

    // thread's 4 local gate-columns -> global j and Gx row base (constant over t)
    int jglob[4];
#pragma unroll
    for (int jj = 0; jj < 4; jj++) {
        int jl = jq * 4 + jj;
        jglob[jj] = (jl >> 3) * 1024 + ct * NJ + (jl & 7);
    }

    for (int t = 0; t < TT; t++) {
        const float* hsrc = (t == 0) ? h0 : g_h[t & 1];
        float acc[4][2];
#pragma unroll
        for (int jj = 0; jj < 4; jj++) { acc[jj][0] = 0.f; acc[jj][1] = 0.f; }

        for (int kc = 0; kc < HH; kc += 128) {
            __syncthreads();   // hs free for rewrite
            {
                int kq = tid & 31;          // float4 index within 128-chunk
                int bg = tid >> 5;          // 0..7
#pragma unroll
                for (int i = 0; i < 8; i++) {
                    int b = bg + 8 * i;
                    float4 v = __ldcg((const float4*)(hsrc + (size_t)b * HH + kc) + kq);
                    float* dst = hs + b * HS_STRIDE + 4 * kq;
                    dst[0] = v.x; dst[1] = v.y; dst[2] = v.z; dst[3] = v.w;
                }
            }
            __syncthreads();

            const float4* Wp0 = (const float4*)(Wsh + (jq * 4 + 0) * HH + kc);
            const float4* Wp1 = (const float4*)(Wsh + (jq * 4 + 1) * HH + kc);
            const float4* Wp2 = (const float4*)(Wsh + (jq * 4 + 2) * HH + kc);
            const float4* Wp3 = (const float4*)(Wsh + (jq * 4 + 3) * HH + kc);
            const float* hpa = hs + b0 * HS_STRIDE;
            const float* hpb = hs + (b0 + 32) * HS_STRIDE;

#pragma unroll 8
            for (int k4 = 0; k4 < 32; k4++) {
                float4 w4[4] = {Wp0[k4], Wp1[k4], Wp2[k4], Wp3[k4]};
                const float* wf = (const float*)&w4[0];
                float hva[4], hvb[4];
#pragma unroll
                for (int c = 0; c < 4; c++) {
                    hva[c] = hpa[k4 * 4 + c];
                    hvb[c] = hpb[k4 * 4 + c];
                }
#pragma unroll
                for (int jj = 0; jj < 4; jj++)
#pragma unroll
                    for (int c = 0; c < 4; c++) {
                        float w = wf[jj * 4 + c];
                        acc[jj][0] += w * hva[c];
                        acc[jj][1] += w * hvb[c];
                    }
            }
        }

        // add precomputed input projection (coalesced: b-contiguous)
#pragma unroll
        for (int jj = 0; jj < 4; jj++) {
            const float* gp = g_gx + ((size_t)t * FOURH + jglob[jj]) * BB;
            acc[jj][0] += __ldcs(gp + b0);
            acc[jj][1] += __ldcs(gp + b0 + 32);
        }

        __syncthreads();   // everyone done reading hs -> safe to write gsh (alias)
#pragma unroll
        for (int jj = 0; jj < 4; jj++) {
            int jl = jq * 4 + jj;
            gsh[jl * 64 + b0]      = acc[jj][0];
            gsh[jl * 64 + b0 + 32] = acc[jj][1];
        }
        __syncthreads();

        // elementwise cell update
        float* hdst = g_h[(t + 1) & 1];
#pragma unroll
        for (int r = 0; r < 2; r++) {
            int item = tid + NTHR * r;
            int b  = item & 63;
            int nl = item >> 6;
            float ig = gsh[(0  + nl) * 64 + b];
            float fg = gsh[(8  + nl) * 64 + b];
            float gg = gsh[(16 + nl) * 64 + b];
            float og = gsh[(24 + nl) * 64 + b];
            float iv = sigmoidf_(ig);
            float fv = sigmoidf_(fg);
            float gv = tanhf(gg);
            float ov = sigmoidf_(og);
            float cv = fv * c_reg[r] + iv * gv;
            float hv = ov * tanhf(cv);
            c_reg[r] = cv;
            int col = ct * NJ + nl;
            out[(size_t)t * BH + b * HH + col] = hv;
            __stcg(hdst + b * HH + col, hv);
            if (t == TT - 1) {
                out[(size_t)TBH + b * HH + col]      = hv;   // h_T
                out[(size_t)TBH + BH + b * HH + col] = cv;   // c_T
            }
        }

        // ---- grid barrier (release h writes, then arrive/spin) ----
        __threadfence();
        __syncthreads();
        if (tid == 0) {
            atomicAdd(&g_bar[t], 1u);
            while (*((volatile unsigned int*)&g_bar[t]) < (unsigned)NCTA) { }
            __threadfence();
        }
        __syncthreads();
    }
}

// ---------------- launch --------------------------------------------------------
extern "C" void kernel_launch(void* const* d_in, const int* in_sizes, int n_in,
                              void* d_out, int out_size) {
    const float* X    = (const float*)d_in[0];   // [T,B,D]
    const float* h0   = (const float*)d_in[1];   // [B,H]
    const float* c0   = (const float*)d_in[2];   // [B,H]
    const float* Wih  = (const float*)d_in[3];   // [4H,D]
    const float* Whh  = (const float*)d_in[4];   // [4H,H]
    const float* b_ih = (const float*)d_in[5];   // [4H]
    const float* b_hh = (const float*)d_in[6];   // [4H]
    float* out = (float*)d_out;

    cudaFuncSetAttribute(lstm_seq_kernel,
                         cudaFuncAttributeMaxDynamicSharedMemorySize, SMEM_P2);

    init_bar_kernel<<<1, TT>>>();

    dim3 g1(FOURH / BN, (TT * BB) / BM);   // (32, 256)
    gemm_xwih_kernel<<<g1, 256>>>(X, Wih, b_ih, b_hh);

    lstm_seq_kernel<<<NCTA, NTHR, SMEM_P2>>>(h0, c0, Whh, out);
}

// round 7
// speedup vs baseline: 1.0017x; 1.0005x over previous
#include <cuda_runtime.h>
#include <cuda_bf16.h>
#include <cstdint>
#include <cstddef>

// Problem dims
#define TT 512
#define BB 64
#define DD 1024
#define HH 1024
#define FOURH 4096
#define TBH (TT * BB * HH)   // 33554432
#define BH  (BB * HH)        // 65536

// Persistent-kernel config
#define NCTA 128          // <= 148 SMs, 1 CTA/SM -> co-resident
#define NTHR 256
#define NJ 8              // hidden columns per CTA (8 * 128 = 1024)

// ---------------- scratch (static device allocations are the allowed path) ----
__device__ float g_gx[(size_t)TT * FOURH * BB];   // 512 MB: Gx[t][j][b]
__device__ float g_h[2][BH];                      // h double buffer
__device__ unsigned int g_bar[TT];                // per-step grid barrier counters

// ---------------- init: zero barrier counters (runs every launch/replay) ------
__global__ void init_bar_kernel() {
    int i = threadIdx.x;
    if (i < TT) g_bar[i] = 0u;
}

// ---------------- Phase 1: Gx[t][j][b] = bias[j] + sum_d X[t,b,d]*W_ih[j,d] ---
// SGEMM: M = T*B (rows m -> (t = m>>6, b = m&63)), N = 4096, K = 1024. fp32.
#define BM 128
#define BN 128
#define BKK 16
__global__ __launch_bounds__(256, 1)
void gemm_xwih_kernel(const float* __restrict__ X,
                      const float* __restrict__ W,     // W_ih [4096][1024]
                      const float* __restrict__ b_ih,
                      const float* __restrict__ b_hh) {
    __shared__ float As[BKK][BM];
    __shared__ float Bs[BKK][BN];

    const int tid = threadIdx.x;
    const int m0 = blockIdx.y * BM;
    const int n0 = blockIdx.x * BN;
    const int tm = (tid >> 4) * 8;   // m micro-offset (8 consecutive rows)
    const int tn = (tid & 15) * 8;   // n micro-offset

    float acc[8][8];
#pragma unroll
    for (int i = 0; i < 8; i++)
#pragma unroll
        for (int j = 0; j < 8; j++) acc[i][j] = 0.f;

    for (int k0 = 0; k0 < DD; k0 += BKK) {
#pragma unroll
        for (int r = 0; r < 2; r++) {
            int idx = tid + r * 256;       // 0..511
            int m   = idx >> 2;            // 0..127
            int kq  = (idx & 3) * 4;       // 0,4,8,12
            float4 va = *(const float4*)(X + (size_t)(m0 + m) * DD + k0 + kq);
            As[kq + 0][m] = va.x; As[kq + 1][m] = va.y;
            As[kq + 2][m] = va.z; As[kq + 3][m] = va.w;
            float4 vb = *(const float4*)(W + (size_t)(n0 + m) * DD + k0 + kq);
            Bs[kq + 0][m] = vb.x; Bs[kq + 1][m] = vb.y;
            Bs[kq + 2][m] = vb.z; Bs[kq + 3][m] = vb.w;
        }
        __syncthreads();

#pragma unroll
        for (int k = 0; k < BKK; k++) {
            float4 a0 = *(const float4*)&As[k][tm];
            float4 a1 = *(const float4*)&As[k][tm + 4];
            float4 c0 = *(const float4*)&Bs[k][tn];
            float4 c1 = *(const float4*)&Bs[k][tn + 4];
            float av[8] = {a0.x, a0.y, a0.z, a0.w, a1.x, a1.y, a1.z, a1.w};
            float bv[8] = {c0.x, c0.y, c0.z, c0.w, c1.x, c1.y, c1.z, c1.w};
#pragma unroll
            for (int i = 0; i < 8; i++)
#pragma unroll
                for (int j = 0; j < 8; j++)
                    acc[i][j] += av[i] * bv[j];
        }
        __syncthreads();
    }

    // Epilogue: Gx[t][j][b], b-contiguous stores (2x float4 per j)
    const int m = m0 + tm;            // 8 consecutive rows, same t (tm % 64 <= 56)
    const int t = m >> 6;
    const int b = m & 63;
#pragma unroll
    for (int j = 0; j < 8; j++) {
        int jg = n0 + tn + j;
        float bias = b_ih[jg] + b_hh[jg];
        float* dst = g_gx + ((size_t)t * FOURH + jg) * BB + b;
        float4 v0 = make_float4(acc[0][j] + bias, acc[1][j] + bias,
                                acc[2][j] + bias, acc[3][j] + bias);
        float4 v1 = make_float4(acc[4][j] + bias, acc[5][j] + bias,
                                acc[6][j] + bias, acc[7][j] + bias);
        *(float4*)dst       = v0;
        *(float4*)(dst + 4) = v1;
    }
}

// ---------------- Phase 2: persistent sequential LSTM --------------------------
// CTA ct owns hidden columns n = ct*8 .. ct*8+7 and all 4 gates of them:
// 32 W_hh rows (128 KB) cached in shared for all 512 steps; c in registers.
#define HS_STRIDE 129
#define SMEM_P2 ((32 * HH + BB * HS_STRIDE) * 4)   // 164096 bytes

__device__ __forceinline__ float sigmoidf_(float x) {
    return 1.0f / (1.0f + __expf(-x));
}

__global__ __launch_bounds__(NTHR, 1)
void lstm_seq_kernel(const float* __restrict__ h0,
                     const float* __restrict__ c0,
                     const float* __restrict__ Whh,   // [4096][1024]
                     float* __restrict__ out) {
    extern __shared__ float sm[];
    float* Wsh = sm;                  // [32][1024]
    float* hs  = sm + 32 * HH;        // [64][129]
    float* gsh = hs;                  // reused as gates [32][64] after compute

    const int tid = threadIdx.x;
    const int ct  = blockIdx.x;       // 0..127
    const int b0  = tid & 31;
    const int jq  = tid >> 5;         // 0..7 -> handles local j = jq*4 .. jq*4+3

    // ---- load W_hh slice into shared (once) ----
    {
        const float4* Wv = (const float4*)Whh;
        float4* Ws4 = (float4*)Wsh;
        for (int idx = tid; idx < 32 * 256; idx += NTHR) {
            int row  = idx >> 8;                 // local j 0..31
            int col  = idx & 255;                // float4 within row
            int gate = row >> 3, nl = row & 7;
            size_t jg = (size_t)gate * 1024 + ct * NJ + nl;
            Ws4[row * 256 + col] = Wv[jg * 256 + col];
        }
    }

    // ---- cell state in registers: items (b, nl) ----
    float c_reg[2];
#pragma unroll
    for (int r = 0; r < 2; r++) {
        int item = tid + NTHR * r;       // 0..511
        int b  = item & 63;
        int nl = item >> 6;              // 0..7
        c_reg[r] = c0[b * HH + ct * NJ + nl];
    }
    __syncthreads();

    // thread's 4 local gate-columns -> global j and Gx row base (constant over t)
    int jglob[4];
#pragma unroll
    for (int jj = 0; jj < 4; jj++) {
        int jl = jq * 4 + jj;
        jglob[jj] = (jl >> 3) * 1024 + ct * NJ + (jl & 7);
    }

    for (int t = 0; t < TT; t++) {
        const float* hsrc = (t == 0) ? h0 : g_h[t & 1];
        float acc[4][2];
#pragma unroll
        for (int jj = 0; jj < 4; jj++) { acc[jj][0] = 0.f; acc[jj][1] = 0.f; }

        for (int kc = 0; kc < HH; kc += 128) {
            __syncthreads();   // hs free for rewrite
            {
                int kq = tid & 31;          // float4 index within 128-chunk
                int bg = tid >> 5;          // 0..7
#pragma unroll
                for (int i = 0; i < 8; i++) {
                    int b = bg + 8 * i;
                    float4 v = __ldcg((const float4*)(hsrc + (size_t)b * HH + kc) + kq);
                    float* dst = hs + b * HS_STRIDE + 4 * kq;
                    dst[0] = v.x; dst[1] = v.y; dst[2] = v.z; dst[3] = v.w;
                }
            }
            __syncthreads();

            const float4* Wp0 = (const float4*)(Wsh + (jq * 4 + 0) * HH + kc);
            const float4* Wp1 = (const float4*)(Wsh + (jq * 4 + 1) * HH + kc);
            const float4* Wp2 = (const float4*)(Wsh + (jq * 4 + 2) * HH + kc);
            const float4* Wp3 = (const float4*)(Wsh + (jq * 4 + 3) * HH + kc);
            const float* hpa = hs + b0 * HS_STRIDE;
            const float* hpb = hs + (b0 + 32) * HS_STRIDE;

#pragma unroll 8
            for (int k4 = 0; k4 < 32; k4++) {
                float4 w4[4] = {Wp0[k4], Wp1[k4], Wp2[k4], Wp3[k4]};
                const float* wf = (const float*)&w4[0];
                float hva[4], hvb[4];
#pragma unroll
                for (int c = 0; c < 4; c++) {
                    hva[c] = hpa[k4 * 4 + c];
                    hvb[c] = hpb[k4 * 4 + c];
                }
#pragma unroll
                for (int jj = 0; jj < 4; jj++)
#pragma unroll
                    for (int c = 0; c < 4; c++) {
                        float w = wf[jj * 4 + c];
                        acc[jj][0] += w * hva[c];
                        acc[jj][1] += w * hvb[c];
                    }
            }
        }

        // add precomputed input projection (coalesced: b-contiguous)
#pragma unroll
        for (int jj = 0; jj < 4; jj++) {
            const float* gp = g_gx + ((size_t)t * FOURH + jglob[jj]) * BB;
            acc[jj][0] += __ldcs(gp + b0);
            acc[jj][1] += __ldcs(gp + b0 + 32);
        }

        __syncthreads();   // everyone done reading hs -> safe to write gsh (alias)
#pragma unroll
        for (int jj = 0; jj < 4; jj++) {
            int jl = jq * 4 + jj;
            gsh[jl * 64 + b0]      = acc[jj][0];
            gsh[jl * 64 + b0 + 32] = acc[jj][1];
        }
        __syncthreads();

        // elementwise cell update
        float* hdst = g_h[(t + 1) & 1];
#pragma unroll
        for (int r = 0; r < 2; r++) {
            int item = tid + NTHR * r;
            int b  = item & 63;
            int nl = item >> 6;
            float ig = gsh[(0  + nl) * 64 + b];
            float fg = gsh[(8  + nl) * 64 + b];
            float gg = gsh[(16 + nl) * 64 + b];
            float og = gsh[(24 + nl) * 64 + b];
            float iv = sigmoidf_(ig);
            float fv = sigmoidf_(fg);
            float gv = tanhf(gg);
            float ov = sigmoidf_(og);
            float cv = fv * c_reg[r] + iv * gv;
            float hv = ov * tanhf(cv);
            c_reg[r] = cv;
            int col = ct * NJ + nl;
            out[(size_t)t * BH + b * HH + col] = hv;
            __stcg(hdst + b * HH + col, hv);
            if (t == TT - 1) {
                out[(size_t)TBH + b * HH + col]      = hv;   // h_T
                out[(size_t)TBH + BH + b * HH + col] = cv;   // c_T
            }
        }

        // ---- grid barrier (release h writes, then arrive/spin) ----
        __threadfence();
        __syncthreads();
        if (tid == 0) {
            atomicAdd(&g_bar[t], 1u);
            while (*((volatile unsigned int*)&g_bar[t]) < (unsigned)NCTA) { }
            __threadfence();
        }
        __syncthreads();
    }
}

// ---------------- launch --------------------------------------------------------
extern "C" void kernel_launch(void* const* d_in, const int* in_sizes, int n_in,
                              void* d_out, int out_size) {
    const float* X    = (const float*)d_in[0];   // [T,B,D]
    const float* h0   = (const float*)d_in[1];   // [B,H]
    const float* c0   = (const float*)d_in[2];   // [B,H]
    const float* Wih  = (const float*)d_in[3];   // [4H,D]
    const float* Whh  = (const float*)d_in[4];   // [4H,H]
    const float* b_ih = (const float*)d_in[5];   // [4H]
    const float* b_hh = (const float*)d_in[6];   // [4H]
    float* out = (float*)d_out;

    cudaFuncSetAttribute(lstm_seq_kernel,
                         cudaFuncAttributeMaxDynamicSharedMemorySize, SMEM_P2);

    init_bar_kernel<<<1, TT>>>();

    dim3 g1(FOURH / BN, (TT * BB) / BM);   // (32, 256)
    gemm_xwih_kernel<<<g1, 256>>>(X, Wih, b_ih, b_hh);

    lstm_seq_kernel<<<NCTA, NTHR, SMEM_P2>>>(h0, c0, Whh, out);
}

// round 8
// speedup vs baseline: 1.0143x; 1.0126x over previous
#include <cuda_runtime.h>
#include <cuda_bf16.h>
#include <cstdint>
#include <cstddef>

// Problem dims
#define TT 512
#define BB 64
#define DD 1024
#define HH 1024
#define FOURH 4096
#define TBH (TT * BB * HH)   // 33554432
#define BH  (BB * HH)        // 65536

// Persistent-kernel config
#define NCTA 128          // <= 148 SMs, 1 CTA/SM -> co-resident
#define NTHR 256

// ---------------- scratch ------------------------------------------------------
__device__ float g_gx[(size_t)TT * FOURH * BB];   // 512 MB: Gx[t][j][b]
__device__ float g_h[2][BH];                      // h double buffer
__device__ unsigned int g_bar[TT];                // per-step grid barrier counters

// ---------------- Phase 1: Gx[t][j][b] = bias[j] + sum_d X[t,b,d]*W_ih[j,d] ---
// SGEMM M = T*B = 32768, N = 4096, K = 1024. Double-buffered smem, reg prefetch,
// 2 CTAs/SM. Also zeroes the phase-2 grid-barrier counters (block 0).
#define BM 128
#define BN 128
#define BKK 16

__global__ __launch_bounds__(256, 2)
void gemm_xwih_kernel(const float* __restrict__ X,
                      const float* __restrict__ W,     // W_ih [4096][1024]
                      const float* __restrict__ b_ih,
                      const float* __restrict__ b_hh) {
    __shared__ float As[2][BKK][BM];
    __shared__ float Bs[2][BKK][BN];

    const int tid = threadIdx.x;

    // reset phase-2 barrier counters (done by one block; gemm completes before lstm)
    if (blockIdx.x == 0 && blockIdx.y == 0) {
        g_bar[tid] = 0u;
        g_bar[tid + 256] = 0u;
    }

    const int m0 = blockIdx.y * BM;
    const int n0 = blockIdx.x * BN;
    const int tm = (tid >> 4) * 8;   // m micro-offset
    const int tn = (tid & 15) * 8;   // n micro-offset

    // loader mapping: idx = tid + r*256 -> (m = idx>>2, kq = (idx&3)*4)
    const int lm0 = tid >> 2;
    const int lkq = (tid & 3) * 4;

    float4 pa[2], pb[2];

    // prologue: load tile 0 into regs, store to buffer 0
    {
        const float* Xp = X + (size_t)(m0 + lm0) * DD + lkq;
        const float* Wp = W + (size_t)(n0 + lm0) * DD + lkq;
        pa[0] = *(const float4*)Xp;            pb[0] = *(const float4*)Wp;
        pa[1] = *(const float4*)(Xp + 64 * DD); pb[1] = *(const float4*)(Wp + 64 * DD);
    }
#pragma unroll
    for (int r = 0; r < 2; r++) {
        int m = lm0 + 64 * r;
        As[0][lkq + 0][m] = pa[r].x; As[0][lkq + 1][m] = pa[r].y;
        As[0][lkq + 2][m] = pa[r].z; As[0][lkq + 3][m] = pa[r].w;
        Bs[0][lkq + 0][m] = pb[r].x; Bs[0][lkq + 1][m] = pb[r].y;
        Bs[0][lkq + 2][m] = pb[r].z; Bs[0][lkq + 3][m] = pb[r].w;
    }
    __syncthreads();

    float acc[8][8];
#pragma unroll
    for (int i = 0; i < 8; i++)
#pragma unroll
        for (int j = 0; j < 8; j++) acc[i][j] = 0.f;

    const int NKT = DD / BKK;   // 64
    for (int kt = 0; kt < NKT; kt++) {
        const int buf = kt & 1;

        // prefetch next tile into registers (latency hides under compute)
        if (kt < NKT - 1) {
            int k0 = (kt + 1) * BKK;
            const float* Xp = X + (size_t)(m0 + lm0) * DD + k0 + lkq;
            const float* Wp = W + (size_t)(n0 + lm0) * DD + k0 + lkq;
            pa[0] = *(const float4*)Xp;            pb[0] = *(const float4*)Wp;
            pa[1] = *(const float4*)(Xp + 64 * DD); pb[1] = *(const float4*)(Wp + 64 * DD);
        }

#pragma unroll
        for (int k = 0; k < BKK; k++) {
            float4 a0 = *(const float4*)&As[buf][k][tm];
            float4 a1 = *(const float4*)&As[buf][k][tm + 4];
            float4 c0 = *(const float4*)&Bs[buf][k][tn];
            float4 c1 = *(const float4*)&Bs[buf][k][tn + 4];
            float av[8] = {a0.x, a0.y, a0.z, a0.w, a1.x, a1.y, a1.z, a1.w};
            float bv[8] = {c0.x, c0.y, c0.z, c0.w, c1.x, c1.y, c1.z, c1.w};
#pragma unroll
            for (int i = 0; i < 8; i++)
#pragma unroll
                for (int j = 0; j < 8; j++)
                    acc[i][j] += av[i] * bv[j];
        }

        if (kt < NKT - 1) {
            const int nb = buf ^ 1;   // safe: all warps finished reading nb last iter
#pragma unroll
            for (int r = 0; r < 2; r++) {
                int m = lm0 + 64 * r;
                As[nb][lkq + 0][m] = pa[r].x; As[nb][lkq + 1][m] = pa[r].y;
                As[nb][lkq + 2][m] = pa[r].z; As[nb][lkq + 3][m] = pa[r].w;
                Bs[nb][lkq + 0][m] = pb[r].x; Bs[nb][lkq + 1][m] = pb[r].y;
                Bs[nb][lkq + 2][m] = pb[r].z; Bs[nb][lkq + 3][m] = pb[r].w;
            }
            __syncthreads();
        }
    }

    // Epilogue: Gx[t][j][b], b-contiguous stores
    const int m = m0 + tm;
    const int t = m >> 6;
    const int b = m & 63;
#pragma unroll
    for (int j = 0; j < 8; j++) {
        int jg = n0 + tn + j;
        float bias = b_ih[jg] + b_hh[jg];
        float* dst = g_gx + ((size_t)t * FOURH + jg) * BB + b;
        float4 v0 = make_float4(acc[0][j] + bias, acc[1][j] + bias,
                                acc[2][j] + bias, acc[3][j] + bias);
        float4 v1 = make_float4(acc[4][j] + bias, acc[5][j] + bias,
                                acc[6][j] + bias, acc[7][j] + bias);
        *(float4*)dst       = v0;
        *(float4*)(dst + 4) = v1;
    }
}

// ---------------- Phase 2: persistent sequential LSTM --------------------------
// CTA ct owns hidden columns ct*8..ct*8+7 and all 4 gates (32 W_hh rows = 128 KB
// cached in smem for all 512 steps). Warp w = (gate jg = w&3, b-half bh = w>>2);
// each thread: 8 gate-columns x 1 batch row -> h smem traffic 0.63 B/FMA (FMA-bound).
#define HS_STRIDE 132          // conflict-free AND 16B-aligned rows
#define HSBUF (64 * HS_STRIDE)
#define GS_STRIDE 65
#define SMEM_P2 ((32 * HH + 2 * HSBUF + 32 * GS_STRIDE) * 4)   // 206976 bytes

__device__ __forceinline__ float sigmoidf_(float x) {
    return 1.0f / (1.0f + __expf(-x));
}

__global__ __launch_bounds__(NTHR, 1)
void lstm_seq_kernel(const float* __restrict__ h0,
                     const float* __restrict__ c0,
                     const float* __restrict__ Whh,   // [4096][1024]
                     float* __restrict__ out) {
    extern __shared__ float sm[];
    float* Wsh = sm;                         // [32][1024]
    float* hsA = sm + 32 * HH;               // [64][132] double buffer
    float* hsB = hsA + HSBUF;
    float* gsh = hsB + HSBUF;                // [32][65]

    const int tid  = threadIdx.x;
    const int ct   = blockIdx.x;             // 0..127
    const int lane = tid & 31;
    const int w    = tid >> 5;               // warp 0..7
    const int jg   = w & 3;                  // gate 0..3
    const int bh   = w >> 2;                 // b-half 0..1
    const int b    = bh * 32 + lane;         // this thread's batch row

    // ---- load W_hh slice into shared (once): row j = gate*8+nl ----
    {
        const float4* Wv = (const float4*)Whh;
        float4* Ws4 = (float4*)Wsh;
        for (int idx = tid; idx < 32 * 256; idx += NTHR) {
            int row  = idx >> 8;
            int col  = idx & 255;
            int gate = row >> 3, nl = row & 7;
            size_t jgl = (size_t)gate * 1024 + ct * 8 + nl;
            Ws4[row * 256 + col] = Wv[jgl * 256 + col];
        }
    }

    // ---- cell state: thread owns (b_e = tid>>2, nl = (tid&3)*2 + {0,1}) ----
    const int be  = tid >> 2;
    const int nl0 = (tid & 3) * 2;
    float c_reg[2];
    c_reg[0] = c0[be * HH + ct * 8 + nl0];
    c_reg[1] = c0[be * HH + ct * 8 + nl0 + 1];
    __syncthreads();

    // W row base for this warp's gate (float4 units)
    const float4* wbase = (const float4*)Wsh + (jg * 8) * 256;

    for (int t = 0; t < TT; t++) {
        const float* hsrc = (t == 0) ? h0 : g_h[t & 1];

        // prologue: load chunk 0 (warp w loads rows w, w+8, ..., w+56)
        float4 v[8];
#pragma unroll
        for (int i = 0; i < 8; i++)
            v[i] = __ldcg((const float4*)(hsrc + (size_t)(w + 8 * i) * HH) + lane);
#pragma unroll
        for (int i = 0; i < 8; i++)
            *(float4*)(hsA + (w + 8 * i) * HS_STRIDE + 4 * lane) = v[i];
        __syncthreads();

        float acc[8];
#pragma unroll
        for (int jj = 0; jj < 8; jj++) acc[jj] = 0.f;

        for (int c = 0; c < 8; c++) {
            // prefetch next chunk into regs (overlaps with compute below)
            if (c < 7) {
                int kc = (c + 1) * 128;
#pragma unroll
                for (int i = 0; i < 8; i++)
                    v[i] = __ldcg((const float4*)(hsrc + (size_t)(w + 8 * i) * HH + kc) + lane);
            }

            const float* cur = (c & 1) ? hsB : hsA;
            const float*  hp = cur + b * HS_STRIDE;
            const float4* wb = wbase + ((c * 128) >> 2);
#pragma unroll 4
            for (int k4 = 0; k4 < 32; k4++) {
                float4 hv = *(const float4*)(hp + 4 * k4);
#pragma unroll
                for (int jj = 0; jj < 8; jj++) {
                    float4 wv = wb[jj * 256 + k4];
                    acc[jj] = fmaf(wv.x, hv.x, acc[jj]);
                    acc[jj] = fmaf(wv.y, hv.y, acc[jj]);
                    acc[jj] = fmaf(wv.z, hv.z, acc[jj]);
                    acc[jj] = fmaf(wv.w, hv.w, acc[jj]);
                }
            }

            if (c < 7) {
                __syncthreads();   // everyone done with the buffer we overwrite
                float* nxt = (c & 1) ? hsA : hsB;
#pragma unroll
                for (int i = 0; i < 8; i++)
                    *(float4*)(nxt + (w + 8 * i) * HS_STRIDE + 4 * lane) = v[i];
                __syncthreads();
            }
        }

        // add precomputed input projection: jglob = jg*1024 + ct*8 + jj
        {
            const float* gp = g_gx + ((size_t)t * FOURH + jg * 1024 + ct * 8) * BB + b;
#pragma unroll
            for (int jj = 0; jj < 8; jj++)
                acc[jj] += __ldcs(gp + jj * BB);
        }

        // exchange gates through smem: gsh[(jg*8+jj)*65 + b]
        __syncthreads();
#pragma unroll
        for (int jj = 0; jj < 8; jj++)
            gsh[(jg * 8 + jj) * GS_STRIDE + b] = acc[jj];
        __syncthreads();

        // elementwise cell update: 2 consecutive nl per thread -> float2 stores
        float* hdst = g_h[(t + 1) & 1];
        float hv2[2], cv2[2];
#pragma unroll
        for (int r = 0; r < 2; r++) {
            int nl = nl0 + r;
            float ig = gsh[(0  + nl) * GS_STRIDE + be];
            float fg = gsh[(8  + nl) * GS_STRIDE + be];
            float gg = gsh[(16 + nl) * GS_STRIDE + be];
            float og = gsh[(24 + nl) * GS_STRIDE + be];
            float iv = sigmoidf_(ig);
            float fv = sigmoidf_(fg);
            float gv = tanhf(gg);
            float ov = sigmoidf_(og);
            float cv = fv * c_reg[r] + iv * gv;
            float hv = ov * tanhf(cv);
            c_reg[r] = cv;
            hv2[r] = hv; cv2[r] = cv;
        }
        {
            size_t off = (size_t)be * HH + ct * 8 + nl0;
            float2 hvv = make_float2(hv2[0], hv2[1]);
            *(float2*)(out + (size_t)t * BH + off) = hvv;
            __stcg((float2*)(hdst + off), hvv);
            if (t == TT - 1) {
                *(float2*)(out + (size_t)TBH + off)      = hvv;                       // h_T
                *(float2*)(out + (size_t)TBH + BH + off) = make_float2(cv2[0], cv2[1]); // c_T
            }
        }

        // ---- grid barrier ----
        __threadfence();
        __syncthreads();
        if (tid == 0) {
            atomicAdd(&g_bar[t], 1u);
            while (*((volatile unsigned int*)&g_bar[t]) < (unsigned)NCTA) { }
            __threadfence();
        }
        __syncthreads();
    }
}

// ---------------- launch --------------------------------------------------------
extern "C" void kernel_launch(void* const* d_in, const int* in_sizes, int n_in,
                              void* d_out, int out_size) {
    const float* X    = (const float*)d_in[0];   // [T,B,D]
    const float* h0   = (const float*)d_in[1];   // [B,H]
    const float* c0   = (const float*)d_in[2];   // [B,H]
    const float* Wih  = (const float*)d_in[3];   // [4H,D]
    const float* Whh  = (const float*)d_in[4];   // [4H,H]
    const float* b_ih = (const float*)d_in[5];   // [4H]
    const float* b_hh = (const float*)d_in[6];   // [4H]
    float* out = (float*)d_out;

    cudaFuncSetAttribute(lstm_seq_kernel,
                         cudaFuncAttributeMaxDynamicSharedMemorySize, SMEM_P2);

    dim3 g1(FOURH / BN, (TT * BB) / BM);   // (32, 256)
    gemm_xwih_kernel<<<g1, 256>>>(X, Wih, b_ih, b_hh);

    lstm_seq_kernel<<<NCTA, NTHR, SMEM_P2>>>(h0, c0, Whh, out);
}

// round 9
// speedup vs baseline: 1.0151x; 1.0008x over previous
#include <cuda_runtime.h>
#include <cuda_bf16.h>
#include <cstdint>
#include <cstddef>

// Problem dims
#define TT 512
#define BB 64
#define DD 1024
#define HH 1024
#define FOURH 4096
#define TBH (TT * BB * HH)   // 33554432
#define BH  (BB * HH)        // 65536

// Persistent-kernel config
#define NCTA 128          // <= 148 SMs, 1 CTA/SM -> co-resident
#define NTHR 256

// ---------------- scratch ------------------------------------------------------
__device__ float g_gx[(size_t)TT * FOURH * BB];   // 512 MB: Gx[t][j][b]
__device__ float g_h[2][BH];                      // h double buffer
__device__ unsigned int g_bar[TT];                // per-step grid barrier counters

// ---------------- Phase 1: Gx[t][j][b] = bias[j] + sum_d X[t,b,d]*W_ih[j,d] ---
// SGEMM M = T*B = 32768, N = 4096, K = 1024. Double-buffered smem, reg prefetch,
// 2 CTAs/SM. Also zeroes the phase-2 grid-barrier counters (block 0).
#define BM 128
#define BN 128
#define BKK 16

__global__ __launch_bounds__(256, 2)
void gemm_xwih_kernel(const float* __restrict__ X,
                      const float* __restrict__ W,     // W_ih [4096][1024]
                      const float* __restrict__ b_ih,
                      const float* __restrict__ b_hh) {
    __shared__ float As[2][BKK][BM];
    __shared__ float Bs[2][BKK][BN];

    const int tid = threadIdx.x;

    // reset phase-2 barrier counters (done by one block; gemm completes before lstm)
    if (blockIdx.x == 0 && blockIdx.y == 0) {
        g_bar[tid] = 0u;
        g_bar[tid + 256] = 0u;
    }

    const int m0 = blockIdx.y * BM;
    const int n0 = blockIdx.x * BN;
    const int tm = (tid >> 4) * 8;   // m micro-offset
    const int tn = (tid & 15) * 8;   // n micro-offset

    // loader mapping: idx = tid + r*256 -> (m = idx>>2, kq = (idx&3)*4)
    const int lm0 = tid >> 2;
    const int lkq = (tid & 3) * 4;

    float4 pa[2], pb[2];

    // prologue: load tile 0 into regs, store to buffer 0
    {
        const float* Xp = X + (size_t)(m0 + lm0) * DD + lkq;
        const float* Wp = W + (size_t)(n0 + lm0) * DD + lkq;
        pa[0] = *(const float4*)Xp;            pb[0] = *(const float4*)Wp;
        pa[1] = *(const float4*)(Xp + 64 * DD); pb[1] = *(const float4*)(Wp + 64 * DD);
    }
#pragma unroll
    for (int r = 0; r < 2; r++) {
        int m = lm0 + 64 * r;
        As[0][lkq + 0][m] = pa[r].x; As[0][lkq + 1][m] = pa[r].y;
        As[0][lkq + 2][m] = pa[r].z; As[0][lkq + 3][m] = pa[r].w;
        Bs[0][lkq + 0][m] = pb[r].x; Bs[0][lkq + 1][m] = pb[r].y;
        Bs[0][lkq + 2][m] = pb[r].z; Bs[0][lkq + 3][m] = pb[r].w;
    }
    __syncthreads();

    float acc[8][8];
#pragma unroll
    for (int i = 0; i < 8; i++)
#pragma unroll
        for (int j = 0; j < 8; j++) acc[i][j] = 0.f;

    const int NKT = DD / BKK;   // 64
    for (int kt = 0; kt < NKT; kt++) {
        const int buf = kt & 1;

        // prefetch next tile into registers (latency hides under compute)
        if (kt < NKT - 1) {
            int k0 = (kt + 1) * BKK;
            const float* Xp = X + (size_t)(m0 + lm0) * DD + k0 + lkq;
            const float* Wp = W + (size_t)(n0 + lm0) * DD + k0 + lkq;
            pa[0] = *(const float4*)Xp;            pb[0] = *(const float4*)Wp;
            pa[1] = *(const float4*)(Xp + 64 * DD); pb[1] = *(const float4*)(Wp + 64 * DD);
        }

#pragma unroll
        for (int k = 0; k < BKK; k++) {
            float4 a0 = *(const float4*)&As[buf][k][tm];
            float4 a1 = *(const float4*)&As[buf][k][tm + 4];
            float4 c0 = *(const float4*)&Bs[buf][k][tn];
            float4 c1 = *(const float4*)&Bs[buf][k][tn + 4];
            float av[8] = {a0.x, a0.y, a0.z, a0.w, a1.x, a1.y, a1.z, a1.w};
            float bv[8] = {c0.x, c0.y, c0.z, c0.w, c1.x, c1.y, c1.z, c1.w};
#pragma unroll
            for (int i = 0; i < 8; i++)
#pragma unroll
                for (int j = 0; j < 8; j++)
                    acc[i][j] += av[i] * bv[j];
        }

        if (kt < NKT - 1) {
            const int nb = buf ^ 1;   // safe: all warps finished reading nb last iter
#pragma unroll
            for (int r = 0; r < 2; r++) {
                int m = lm0 + 64 * r;
                As[nb][lkq + 0][m] = pa[r].x; As[nb][lkq + 1][m] = pa[r].y;
                As[nb][lkq + 2][m] = pa[r].z; As[nb][lkq + 3][m] = pa[r].w;
                Bs[nb][lkq + 0][m] = pb[r].x; Bs[nb][lkq + 1][m] = pb[r].y;
                Bs[nb][lkq + 2][m] = pb[r].z; Bs[nb][lkq + 3][m] = pb[r].w;
            }
            __syncthreads();
        }
    }

    // Epilogue: Gx[t][j][b], b-contiguous stores
    const int m = m0 + tm;
    const int t = m >> 6;
    const int b = m & 63;
#pragma unroll
    for (int j = 0; j < 8; j++) {
        int jg = n0 + tn + j;
        float bias = b_ih[jg] + b_hh[jg];
        float* dst = g_gx + ((size_t)t * FOURH + jg) * BB + b;
        float4 v0 = make_float4(acc[0][j] + bias, acc[1][j] + bias,
                                acc[2][j] + bias, acc[3][j] + bias);
        float4 v1 = make_float4(acc[4][j] + bias, acc[5][j] + bias,
                                acc[6][j] + bias, acc[7][j] + bias);
        *(float4*)dst       = v0;
        *(float4*)(dst + 4) = v1;
    }
}

// ---------------- Phase 2: persistent sequential LSTM --------------------------
// CTA ct owns hidden columns ct*8..ct*8+7 and all 4 gates (32 W_hh rows = 128 KB
// cached in smem for all 512 steps). Warp w = (gate jg = w&3, b-half bh = w>>2);
// each thread: 8 gate-columns x 1 batch row -> h smem traffic 0.63 B/FMA (FMA-bound).
#define HS_STRIDE 132          // conflict-free AND 16B-aligned rows
#define HSBUF (64 * HS_STRIDE)
#define GS_STRIDE 65
#define SMEM_P2 ((32 * HH + 2 * HSBUF + 32 * GS_STRIDE) * 4)   // 206976 bytes

__device__ __forceinline__ float sigmoidf_(float x) {
    return 1.0f / (1.0f + __expf(-x));
}

__global__ __launch_bounds__(NTHR, 1)
void lstm_seq_kernel(const float* __restrict__ h0,
                     const float* __restrict__ c0,
                     const float* __restrict__ Whh,   // [4096][1024]
                     float* __restrict__ out) {
    extern __shared__ float sm[];
    float* Wsh = sm;                         // [32][1024]
    float* hsA = sm + 32 * HH;               // [64][132] double buffer
    float* hsB = hsA + HSBUF;
    float* gsh = hsB + HSBUF;                // [32][65]

    const int tid  = threadIdx.x;
    const int ct   = blockIdx.x;             // 0..127
    const int lane = tid & 31;
    const int w    = tid >> 5;               // warp 0..7
    const int jg   = w & 3;                  // gate 0..3
    const int bh   = w >> 2;                 // b-half 0..1
    const int b    = bh * 32 + lane;         // this thread's batch row

    // ---- load W_hh slice into shared (once): row j = gate*8+nl ----
    {
        const float4* Wv = (const float4*)Whh;
        float4* Ws4 = (float4*)Wsh;
        for (int idx = tid; idx < 32 * 256; idx += NTHR) {
            int row  = idx >> 8;
            int col  = idx & 255;
            int gate = row >> 3, nl = row & 7;
            size_t jgl = (size_t)gate * 1024 + ct * 8 + nl;
            Ws4[row * 256 + col] = Wv[jgl * 256 + col];
        }
    }

    // ---- cell state: thread owns (b_e = tid>>2, nl = (tid&3)*2 + {0,1}) ----
    const int be  = tid >> 2;
    const int nl0 = (tid & 3) * 2;
    float c_reg[2];
    c_reg[0] = c0[be * HH + ct * 8 + nl0];
    c_reg[1] = c0[be * HH + ct * 8 + nl0 + 1];
    __syncthreads();

    // W row base for this warp's gate (float4 units)
    const float4* wbase = (const float4*)Wsh + (jg * 8) * 256;

    for (int t = 0; t < TT; t++) {
        const float* hsrc = (t == 0) ? h0 : g_h[t & 1];

        // prologue: load chunk 0 (warp w loads rows w, w+8, ..., w+56)
        float4 v[8];
#pragma unroll
        for (int i = 0; i < 8; i++)
            v[i] = __ldcg((const float4*)(hsrc + (size_t)(w + 8 * i) * HH) + lane);
#pragma unroll
        for (int i = 0; i < 8; i++)
            *(float4*)(hsA + (w + 8 * i) * HS_STRIDE + 4 * lane) = v[i];
        __syncthreads();

        float acc[8];
#pragma unroll
        for (int jj = 0; jj < 8; jj++) acc[jj] = 0.f;

        for (int c = 0; c < 8; c++) {
            // prefetch next chunk into regs (overlaps with compute below)
            if (c < 7) {
                int kc = (c + 1) * 128;
#pragma unroll
                for (int i = 0; i < 8; i++)
                    v[i] = __ldcg((const float4*)(hsrc + (size_t)(w + 8 * i) * HH + kc) + lane);
            }

            const float* cur = (c & 1) ? hsB : hsA;
            const float*  hp = cur + b * HS_STRIDE;
            const float4* wb = wbase + ((c * 128) >> 2);
#pragma unroll 4
            for (int k4 = 0; k4 < 32; k4++) {
                float4 hv = *(const float4*)(hp + 4 * k4);
#pragma unroll
                for (int jj = 0; jj < 8; jj++) {
                    float4 wv = wb[jj * 256 + k4];
                    acc[jj] = fmaf(wv.x, hv.x, acc[jj]);
                    acc[jj] = fmaf(wv.y, hv.y, acc[jj]);
                    acc[jj] = fmaf(wv.z, hv.z, acc[jj]);
                    acc[jj] = fmaf(wv.w, hv.w, acc[jj]);
                }
            }

            if (c < 7) {
                __syncthreads();   // everyone done with the buffer we overwrite
                float* nxt = (c & 1) ? hsA : hsB;
#pragma unroll
                for (int i = 0; i < 8; i++)
                    *(float4*)(nxt + (w + 8 * i) * HS_STRIDE + 4 * lane) = v[i];
                __syncthreads();
            }
        }

        // add precomputed input projection: jglob = jg*1024 + ct*8 + jj
        {
            const float* gp = g_gx + ((size_t)t * FOURH + jg * 1024 + ct * 8) * BB + b;
#pragma unroll
            for (int jj = 0; jj < 8; jj++)
                acc[jj] += __ldcs(gp + jj * BB);
        }

        // exchange gates through smem: gsh[(jg*8+jj)*65 + b]
        __syncthreads();
#pragma unroll
        for (int jj = 0; jj < 8; jj++)
            gsh[(jg * 8 + jj) * GS_STRIDE + b] = acc[jj];
        __syncthreads();

        // elementwise cell update: 2 consecutive nl per thread -> float2 stores
        float* hdst = g_h[(t + 1) & 1];
        float hv2[2], cv2[2];
#pragma unroll
        for (int r = 0; r < 2; r++) {
            int nl = nl0 + r;
            float ig = gsh[(0  + nl) * GS_STRIDE + be];
            float fg = gsh[(8  + nl) * GS_STRIDE + be];
            float gg = gsh[(16 + nl) * GS_STRIDE + be];
            float og = gsh[(24 + nl) * GS_STRIDE + be];
            float iv = sigmoidf_(ig);
            float fv = sigmoidf_(fg);
            float gv = tanhf(gg);
            float ov = sigmoidf_(og);
            float cv = fv * c_reg[r] + iv * gv;
            float hv = ov * tanhf(cv);
            c_reg[r] = cv;
            hv2[r] = hv; cv2[r] = cv;
        }
        {
            size_t off = (size_t)be * HH + ct * 8 + nl0;
            float2 hvv = make_float2(hv2[0], hv2[1]);
            *(float2*)(out + (size_t)t * BH + off) = hvv;
            __stcg((float2*)(hdst + off), hvv);
            if (t == TT - 1) {
                *(float2*)(out + (size_t)TBH + off)      = hvv;                       // h_T
                *(float2*)(out + (size_t)TBH + BH + off) = make_float2(cv2[0], cv2[1]); // c_T
            }
        }

        // ---- grid barrier ----
        __threadfence();
        __syncthreads();
        if (tid == 0) {
            atomicAdd(&g_bar[t], 1u);
            while (*((volatile unsigned int*)&g_bar[t]) < (unsigned)NCTA) { }
            __threadfence();
        }
        __syncthreads();
    }
}

// ---------------- launch --------------------------------------------------------
extern "C" void kernel_launch(void* const* d_in, const int* in_sizes, int n_in,
                              void* d_out, int out_size) {
    const float* X    = (const float*)d_in[0];   // [T,B,D]
    const float* h0   = (const float*)d_in[1];   // [B,H]
    const float* c0   = (const float*)d_in[2];   // [B,H]
    const float* Wih  = (const float*)d_in[3];   // [4H,D]
    const float* Whh  = (const float*)d_in[4];   // [4H,H]
    const float* b_ih = (const float*)d_in[5];   // [4H]
    const float* b_hh = (const float*)d_in[6];   // [4H]
    float* out = (float*)d_out;

    cudaFuncSetAttribute(lstm_seq_kernel,
                         cudaFuncAttributeMaxDynamicSharedMemorySize, SMEM_P2);

    dim3 g1(FOURH / BN, (TT * BB) / BM);   // (32, 256)
    gemm_xwih_kernel<<<g1, 256>>>(X, Wih, b_ih, b_hh);

    lstm_seq_kernel<<<NCTA, NTHR, SMEM_P2>>>(h0, c0, Whh, out);
}